// round 11
// baseline (speedup 1.0000x reference)
#include <cuda_runtime.h>
#include <cstdint>

#define NPTS   60000
#define KOFF   27
#define CIN    2
#define COUT   64
#define BB     2
#define DD     12
#define HH     200
#define WW     200
#define CELLS  960000        // 2*12*200*200
#define EPS_LN 1e-5f

#define ROWS_TOTAL (BB * DD * HH)        // 4800 blocks
#define WARPS_PER_BLOCK 10
#define THREADS (WARPS_PER_BLOCK * 32)   // 320
#define CELLS_PER_WARP 20                // 10 warps x 20 = 200 = WW
#define CHUNK 4                          // 2 pairs per phase

#define GROW 202                         // padded row: [-1 | 200 | -1]
#define EMPTY16 0xFFFFu

// Dense cell -> point-id lookup grid (3.84 MB, L2-resident). -1 = empty.
__device__ int g_pointgrid[CELLS];
// Channel-mean weight vectors: wbar[j] = (1/64) sum_q w_jq  (2-vec).
__device__ float2 g_wbar[KOFF];

// --------------------------------------------------------------------------
// Kernel 1: init point grid to -1.
// --------------------------------------------------------------------------
__global__ void init_grid_kernel() {
    int i = blockIdx.x * blockDim.x + threadIdx.x;
    if (i < CELLS / 4)
        reinterpret_cast<int4*>(g_pointgrid)[i] = make_int4(-1, -1, -1, -1);
}

// --------------------------------------------------------------------------
// Kernel 2: fill point grid. scat[13*NPTS + n] is point n's own cell index.
// --------------------------------------------------------------------------
__global__ void fill_grid_kernel(const int* __restrict__ scat) {
    int n = blockIdx.x * blockDim.x + threadIdx.x;
    if (n < NPTS)
        g_pointgrid[scat[13 * NPTS + n]] = n;
}

// --------------------------------------------------------------------------
// Kernel 2b: precompute wbar (27 threads, trivial).
// --------------------------------------------------------------------------
__global__ void wbar_kernel(const float* __restrict__ weight) {  // [27,2,64]
    int t = threadIdx.x;
    if (t < KOFF) {
        float s0 = 0.f, s1 = 0.f;
        #pragma unroll 8
        for (int q = 0; q < COUT; q++) {
            s0 += weight[(t * 2 + 0) * COUT + q];
            s1 += weight[(t * 2 + 1) * COUT + q];
        }
        g_wbar[t] = make_float2(s0 * (1.f / COUT), s1 * (1.f / COUT));
    }
}

// --------------------------------------------------------------------------
// Kernel 3: fused gather-conv + LayerNorm + ReLU.
// One block per (b, z, y) row. HALF-WARP per cell: lanes 0-15 serve cell A,
// lanes 16-31 serve cell B; each lane owns 4 consecutive channels. Every
// warp-collective (hit loop, butterfly over 16 lanes, epilogue, STG.128)
// is shared by two cells. mean analytic via wbar; var = E[a^2]-mean^2.
// --------------------------------------------------------------------------
__global__ __launch_bounds__(THREADS, 5) void fused_kernel(
        const float2* __restrict__ feat,     // [NPTS] as float2
        const float4* __restrict__ weight4,  // float4 view of [27,2,64]
        const float*  __restrict__ gamma,
        const float*  __restrict__ beta,
        float* __restrict__ out) {           // [CELLS, 64]
    // swq[j][2*l16+cin] = weights of channels [4*l16,4*l16+4) for (j,cin);
    // swq[j][32] = (wbar_j.x, wbar_j.y, 0, 0)
    __shared__ float4 swq[KOFF][34];                           // 14688 B
    __shared__ unsigned short sgrid[9 * GROW];                 //  3636 B
    __shared__ float2 sfeat[WARPS_PER_BLOCK][CHUNK][28];       //  8960 B

    // decode row
    const int row = blockIdx.x;          // (b*DD + z)*HH + y
    const int y   = row % HH;
    const int bz  = row / HH;            // b*DD + z
    const int z   = bz % DD;
    const int rowbase = row * WW;        // linear cell index of x=0

    // ---- stage packed weights ----
    for (int i = threadIdx.x; i < KOFF * 32; i += THREADS) {
        const int j = i >> 5, t = i & 31;
        const int cin = t & 1, l16 = t >> 1;
        swq[j][2 * l16 + cin] = weight4[(j * 2 + cin) * (COUT / 4) + l16];
    }
    if (threadIdx.x < KOFF) {
        const float2 wb = g_wbar[threadIdx.x];
        swq[threadIdx.x][32] = make_float4(wb.x, wb.y, 0.f, 0.f);
    }

    // ---- stage 9 neighbor grid rows with halo (uint16, 0xFFFF = empty) ----
    for (int i = threadIdx.x; i < 9 * GROW; i += THREADS) {
        const int r  = i / GROW;         // 0..8 -> (dz+1)*3 + (dy+1)
        const int c  = i - r * GROW;     // 0..201 -> x = c-1
        const int dz = r / 3 - 1;
        const int dy = r % 3 - 1;
        const int nz = z + dz, ny = y + dy, nx = c - 1;
        int v = -1;
        if ((unsigned)nz < DD && (unsigned)ny < HH && (unsigned)nx < WW)
            v = g_pointgrid[rowbase + (dz * HH + dy) * WW + nx];
        sgrid[i] = (v < 0) ? (unsigned short)EMPTY16 : (unsigned short)v;
    }
    __syncthreads();

    const int lane = threadIdx.x & 31;
    const int wib  = threadIdx.x >> 5;
    const int l16  = lane & 15;
    const int half = lane >> 4;          // 0 -> even cell, 1 -> odd cell

    const float4 gg = reinterpret_cast<const float4*>(gamma)[l16];
    const float4 bb = reinterpret_cast<const float4*>(beta)[l16];

    // lane -> (k, smem probe base) for the probe phase (lanes 0..26)
    const int dxl   = lane % 3;
    const int srow  = (lane < KOFF) ? (lane / 3) : 0;
    const int pbase = srow * GROW + dxl;
    const bool probing = (lane < KOFF);

    const int x0 = wib * CELLS_PER_WARP;

    for (int c0 = 0; c0 < CELLS_PER_WARP; c0 += CHUNK) {
        // ---- phase 1: probes (LDS.U16), 4 cells ----
        unsigned pt[CHUNK];
        #pragma unroll
        for (int ci = 0; ci < CHUNK; ci++) {
            const int x = x0 + c0 + ci;
            pt[ci] = probing ? (unsigned)sgrid[pbase + x] : EMPTY16;
        }

        // ---- phase 2: ballots + feature gather -> smem bounce ----
        unsigned act[CHUNK];
        #pragma unroll
        for (int ci = 0; ci < CHUNK; ci++)
            act[ci] = __ballot_sync(0xffffffffu, pt[ci] != EMPTY16);

        const unsigned any = act[0] | act[1] | act[2] | act[3];
        const int cellbase = rowbase + x0 + c0;
        if (any == 0u) {                 // whole chunk inactive: clear poison
            #pragma unroll
            for (int pr = 0; pr < CHUNK / 2; pr++) {
                const int cell = cellbase + pr * 2 + half;
                float4* po = reinterpret_cast<float4*>(out + (size_t)cell * COUT) + l16;
                __stcs(po, make_float4(0.f, 0.f, 0.f, 0.f));
            }
            continue;
        }

        #pragma unroll
        for (int ci = 0; ci < CHUNK; ci++)
            if (pt[ci] != EMPTY16)
                sfeat[wib][ci][lane] = __ldg(&feat[pt[ci]]);
        __syncwarp();

        // ---- phase 3: half-warp hit loops (2 pairs) ----
        float4 A[2];                 // 4 channels for this lane's cell
        float MEAN[2], SQ[2];
        #pragma unroll
        for (int pr = 0; pr < 2; pr++) {
            const int myci = pr * 2 + half;
            unsigned mask = act[myci];
            float4 a = make_float4(0.f, 0.f, 0.f, 0.f);
            float mean = 0.f;
            while (mask) {           // divergent between halves; reconverges
                const int j = __ffs(mask) - 1;
                mask &= mask - 1;
                const float2 f  = sfeat[wib][myci][j];
                const float4* basep = &swq[j][0];
                const float4 w0 = basep[2 * l16 + 0];
                const float4 w1 = basep[2 * l16 + 1];
                const float4 wb = basep[32];
                a.x = fmaf(f.x, w0.x, fmaf(f.y, w1.x, a.x));
                a.y = fmaf(f.x, w0.y, fmaf(f.y, w1.y, a.y));
                a.z = fmaf(f.x, w0.z, fmaf(f.y, w1.z, a.z));
                a.w = fmaf(f.x, w0.w, fmaf(f.y, w1.w, a.w));
                mean = fmaf(f.x, wb.x, fmaf(f.y, wb.y, mean));
            }
            A[pr] = a;
            MEAN[pr] = mean;
            SQ[pr] = fmaf(a.x, a.x, fmaf(a.y, a.y, fmaf(a.z, a.z, a.w * a.w)));
        }

        // ---- phase 4: butterfly over 16 lanes, both pairs interleaved ----
        #pragma unroll
        for (int o = 8; o > 0; o >>= 1) {
            SQ[0] += __shfl_xor_sync(0xffffffffu, SQ[0], o);
            SQ[1] += __shfl_xor_sync(0xffffffffu, SQ[1], o);
        }

        // ---- phase 5: normalize + relu + streaming STG.128 ----
        #pragma unroll
        for (int pr = 0; pr < 2; pr++) {
            const int myci = pr * 2 + half;
            const float var = fmaf(-MEAN[pr], MEAN[pr], SQ[pr] * (1.f / COUT));
            const float inv = rsqrtf(var + EPS_LN);
            float4 r;
            r.x = fmaxf(fmaf((A[pr].x - MEAN[pr]) * inv, gg.x, bb.x), 0.f);
            r.y = fmaxf(fmaf((A[pr].y - MEAN[pr]) * inv, gg.y, bb.y), 0.f);
            r.z = fmaxf(fmaf((A[pr].z - MEAN[pr]) * inv, gg.z, bb.z), 0.f);
            r.w = fmaxf(fmaf((A[pr].w - MEAN[pr]) * inv, gg.w, bb.w), 0.f);
            if (act[myci] == 0u) r = make_float4(0.f, 0.f, 0.f, 0.f);
            const int cell = cellbase + myci;
            float4* po = reinterpret_cast<float4*>(out + (size_t)cell * COUT) + l16;
            __stcs(po, r);
        }
    }
}

// --------------------------------------------------------------------------
extern "C" void kernel_launch(void* const* d_in, const int* in_sizes, int n_in,
                              void* d_out, int out_size) {
    const float* feat   = (const float*)d_in[0];   // [60000, 2]
    const float* weight = (const float*)d_in[1];   // [27, 2, 64]
    const float* gamma  = (const float*)d_in[2];   // [64]
    const float* beta   = (const float*)d_in[3];   // [64]
    const int*   scat   = (const int*)d_in[4];     // [27, 60000]
    float* out = (float*)d_out;                    // [960000, 64]

    init_grid_kernel<<<(CELLS / 4 + 255) / 256, 256>>>();
    fill_grid_kernel<<<(NPTS + 255) / 256, 256>>>(scat);
    wbar_kernel<<<1, 32>>>(weight);
    fused_kernel<<<ROWS_TOTAL, THREADS>>>(
        (const float2*)feat, (const float4*)weight, gamma, beta, out);
}